// round 9
// baseline (speedup 1.0000x reference)
#include <cuda_runtime.h>
#include <math.h>

// ---------------------------------------------------------------------------
// Problem constants
// ---------------------------------------------------------------------------
namespace {
constexpr int Bc = 64, Tc = 32, TMAX = 31;
constexpr int Fc = 512, Lc = 196, Ec = 512, Hc = 512, Ac = 512, Vc = 10000;
constexpr int NCAT = 3072;            // de(512) | fbeta(512) | hh gates(2048)
constexpr int NSPLIT = 4;             // split-K factor for step GEMMs
constexpr long long PRED_SZ = (long long)Bc * TMAX * Vc;   // 19,840,000
}

// ---------------------------------------------------------------------------
// Static scratch (no allocations allowed)
// ---------------------------------------------------------------------------
__device__ float g_en_att[Bc * Lc * Ac];          // [B*L, A]
__device__ float g_meanf[Bc * Fc];
__device__ float g_hc[Bc * 1024];                 // h = cols[0:512), c = cols[512:1024)
__device__ float g_hp[NSPLIT * Bc * NCAT];        // hproj split-K partials
__device__ float g_ip[NSPLIT * Bc * 1024];        // init GEMM partials
__device__ float g_xz[Bc * Fc];                   // gated context z
__device__ float g_Wcat[NCAT * Hc];               // [W_dec ; W_fbeta ; W_hh]
__device__ float g_bcat[NCAT];
__device__ float g_Winit[1024 * Fc];              // [W_init_h ; W_init_c]
__device__ float g_binit[1024];
__device__ float g_xemb[TMAX * Bc * Ec];          // gathered embeddings
__device__ float g_embg[TMAX * Bc * 2048];        // emb @ W_ih_emb^T
__device__ float g_hnew_all[TMAX * Bc * Hc];      // unmasked h_new per step

__device__ __forceinline__ float tanh_fast(float x) {
    float y;
    asm("tanh.approx.f32 %0, %1;" : "=f"(y) : "f"(x));
    return y;
}
__device__ __forceinline__ float sigmoid_fast(float x) {
    return 1.0f / (1.0f + __expf(-x));
}
__device__ __forceinline__ unsigned f2tf32(float x) {
    unsigned r;
    asm("cvt.rna.tf32.f32 %0, %1;" : "=r"(r) : "f"(x));
    return r;
}

// ---------------------------------------------------------------------------
// Weight packers
// ---------------------------------------------------------------------------
__global__ void build_cat(const float* __restrict__ Wdec,
                          const float* __restrict__ Wfb,
                          const float* __restrict__ Whh,
                          const float* __restrict__ bdec,
                          const float* __restrict__ bfb,
                          const float* __restrict__ bih,
                          const float* __restrict__ bhh)
{
    int idx = blockIdx.x * 256 + threadIdx.x;
    if (idx < NCAT * Hc) {
        int n = idx / Hc, k = idx % Hc;
        float v;
        if (n < 512)       v = Wdec[n * Hc + k];
        else if (n < 1024) v = Wfb[(n - 512) * Hc + k];
        else               v = Whh[(n - 1024) * Hc + k];
        g_Wcat[idx] = v;
    }
    if (idx < NCAT) {
        float v;
        if (idx < 512)       v = bdec[idx];
        else if (idx < 1024) v = bfb[idx - 512];
        else                 v = bih[idx - 1024] + bhh[idx - 1024];
        g_bcat[idx] = v;
    }
}

__global__ void build_init(const float* __restrict__ Wih_,
                           const float* __restrict__ Wic_,
                           const float* __restrict__ bih_,
                           const float* __restrict__ bic_)
{
    int idx = blockIdx.x * 256 + threadIdx.x;
    if (idx < 1024 * Fc) {
        int n = idx / Fc, k = idx % Fc;
        g_Winit[idx] = (n < 512) ? Wih_[n * Fc + k] : Wic_[(n - 512) * Fc + k];
    }
    if (idx < 1024)
        g_binit[idx] = (idx < 512) ? bih_[idx] : bic_[idx - 512];
}

// mean over the L axis of the ORIGINAL [B, F, L] layout
__global__ void mean_feat(const float* __restrict__ feat)
{
    int b = blockIdx.x, f = threadIdx.x;   // 512 threads
    const float* p = feat + (size_t)b * Fc * Lc + (size_t)f * Lc;
    float s = 0.f;
    #pragma unroll 4
    for (int l = 0; l < Lc; ++l) s += p[l];
    g_meanf[b * Fc + f] = s * (1.0f / (float)Lc);
}

// gather embeddings for ALL steps
__global__ void embed_all(const float* __restrict__ Wemb,
                          const int* __restrict__ captions)
{
    int b = blockIdx.x, t = blockIdx.y, e = threadIdx.x;   // 512 threads
    int tok = captions[b * Tc + t];
    g_xemb[((size_t)t * Bc + b) * Ec + e] = Wemb[(size_t)tok * Ec + e];
}

// h0/c0 combine: g_hc = sum of split-K partials + bias
__global__ void combine_init()
{
    int b = blockIdx.x, n = threadIdx.x;   // 1024 threads
    float s = g_binit[n];
    #pragma unroll
    for (int sp = 0; sp < NSPLIT; ++sp)
        s += g_ip[((size_t)sp * Bc + b) * 1024 + n];
    g_hc[b * 1024 + n] = s;
}

// ---------------------------------------------------------------------------
// Split-K fp32 GEMM: Cpart[s][64, N] = A[64, kslice] @ B[N, kslice]^T
// BM=64, BN=32, BK=16, 256 threads. grid = (N/32, NSPLIT).
// ---------------------------------------------------------------------------
__global__ __launch_bounds__(256) void gemm_splitk(
    int N, int K,
    const float* __restrict__ A, int ldA,
    const float* __restrict__ B, int ldB,
    float* __restrict__ Cpart, int ldC)
{
    constexpr int BK = 16;
    const int kslice = K / NSPLIT;
    const int s  = blockIdx.y;
    const int bn = blockIdx.x * 32;
    const int koff = s * kslice;

    __shared__ float As[2][BK][64];
    __shared__ float Bs[2][BK][32];

    const int tid = threadIdx.x;
    const int tx = tid & 15, ty = tid >> 4;
    const int arow = tid >> 2, acol = (tid & 3) * 4;
    const int brow = tid >> 3, bcol = (tid & 7) * 2;

    const float* aptr = A + (size_t)arow * ldA + koff + acol;
    const float* bptr = B + (size_t)(bn + brow) * ldB + koff + bcol;

    float acc[4][2];
    #pragma unroll
    for (int i = 0; i < 4; ++i) { acc[i][0] = 0.f; acc[i][1] = 0.f; }

    float4 av = *reinterpret_cast<const float4*>(aptr);
    float2 bv = *reinterpret_cast<const float2*>(bptr);
    As[0][acol + 0][arow] = av.x; As[0][acol + 1][arow] = av.y;
    As[0][acol + 2][arow] = av.z; As[0][acol + 3][arow] = av.w;
    Bs[0][bcol + 0][brow] = bv.x; Bs[0][bcol + 1][brow] = bv.y;
    __syncthreads();

    const int nt = kslice / BK;
    for (int it = 0; it < nt; ++it) {
        const int cur = it & 1;
        if (it + 1 < nt) {
            av = *reinterpret_cast<const float4*>(aptr + (it + 1) * BK);
            bv = *reinterpret_cast<const float2*>(bptr + (it + 1) * BK);
        }
        #pragma unroll
        for (int k = 0; k < BK; ++k) {
            float4 a4 = *reinterpret_cast<const float4*>(&As[cur][k][ty * 4]);
            float2 b2 = *reinterpret_cast<const float2*>(&Bs[cur][k][tx * 2]);
            acc[0][0] += a4.x * b2.x; acc[0][1] += a4.x * b2.y;
            acc[1][0] += a4.y * b2.x; acc[1][1] += a4.y * b2.y;
            acc[2][0] += a4.z * b2.x; acc[2][1] += a4.z * b2.y;
            acc[3][0] += a4.w * b2.x; acc[3][1] += a4.w * b2.y;
        }
        if (it + 1 < nt) {
            const int nxt = cur ^ 1;
            As[nxt][acol + 0][arow] = av.x; As[nxt][acol + 1][arow] = av.y;
            As[nxt][acol + 2][arow] = av.z; As[nxt][acol + 3][arow] = av.w;
            Bs[nxt][bcol + 0][brow] = bv.x; Bs[nxt][bcol + 1][brow] = bv.y;
        }
        __syncthreads();
    }

    #pragma unroll
    for (int i = 0; i < 4; ++i) {
        float* dst = Cpart + ((size_t)s * 64 + ty * 4 + i) * ldC + bn + tx * 2;
        dst[0] = acc[i][0];
        dst[1] = acc[i][1];
    }
}

// ---------------------------------------------------------------------------
// att_hh: blocks 0..63 = fused attention for batch b
//         blocks 64..319 = split-K GEMM for the hh-gates (Wcat rows 1024:3072)
// ---------------------------------------------------------------------------
__global__ __launch_bounds__(256) void att_hh(
    const float* __restrict__ features,
    const float* __restrict__ Wfull,
    const int*   __restrict__ lengths,
    float* __restrict__ alpha_out, int t)
{
    const int tid = threadIdx.x;

    __shared__ float s_de[Ac];
    __shared__ float s_wf[Ac];
    __shared__ float s_sc[256];
    __shared__ float s_red[256];
    __shared__ float As[2][16][64];
    __shared__ float Bs[2][16][32];

    if (blockIdx.x >= 64) {
        // ---- hh-gates split-K GEMM: g_hp[s][b][1024+.] = h @ Whh-part^T ----
        const int tile = blockIdx.x - 64;          // 0..255
        const int s = tile >> 6, tn = tile & 63;
        const int bn = tn * 32;
        const int koff = s * 128;                  // kslice = 512/4

        const int tx = tid & 15, ty = tid >> 4;
        const int arow = tid >> 2, acol = (tid & 3) * 4;
        const int brow = tid >> 3, bcol = (tid & 7) * 2;

        const float* aptr = g_hc + (size_t)arow * 1024 + koff + acol;
        const float* bptr = g_Wcat + (size_t)(1024 + bn + brow) * Hc + koff + bcol;

        float acc[4][2];
        #pragma unroll
        for (int i = 0; i < 4; ++i) { acc[i][0] = 0.f; acc[i][1] = 0.f; }

        float4 av = *reinterpret_cast<const float4*>(aptr);
        float2 bv = *reinterpret_cast<const float2*>(bptr);
        As[0][acol + 0][arow] = av.x; As[0][acol + 1][arow] = av.y;
        As[0][acol + 2][arow] = av.z; As[0][acol + 3][arow] = av.w;
        Bs[0][bcol + 0][brow] = bv.x; Bs[0][bcol + 1][brow] = bv.y;
        __syncthreads();

        const int nt = 128 / 16;
        for (int it = 0; it < nt; ++it) {
            const int cur = it & 1;
            if (it + 1 < nt) {
                av = *reinterpret_cast<const float4*>(aptr + (it + 1) * 16);
                bv = *reinterpret_cast<const float2*>(bptr + (it + 1) * 16);
            }
            #pragma unroll
            for (int k = 0; k < 16; ++k) {
                float4 a4 = *reinterpret_cast<const float4*>(&As[cur][k][ty * 4]);
                float2 b2 = *reinterpret_cast<const float2*>(&Bs[cur][k][tx * 2]);
                acc[0][0] += a4.x * b2.x; acc[0][1] += a4.x * b2.y;
                acc[1][0] += a4.y * b2.x; acc[1][1] += a4.y * b2.y;
                acc[2][0] += a4.z * b2.x; acc[2][1] += a4.z * b2.y;
                acc[3][0] += a4.w * b2.x; acc[3][1] += a4.w * b2.y;
            }
            if (it + 1 < nt) {
                const int nxt = cur ^ 1;
                As[nxt][acol + 0][arow] = av.x; As[nxt][acol + 1][arow] = av.y;
                As[nxt][acol + 2][arow] = av.z; As[nxt][acol + 3][arow] = av.w;
                Bs[nxt][bcol + 0][brow] = bv.x; Bs[nxt][bcol + 1][brow] = bv.y;
            }
            __syncthreads();
        }

        #pragma unroll
        for (int i = 0; i < 4; ++i) {
            float* dst = g_hp + ((size_t)s * 64 + ty * 4 + i) * NCAT
                              + 1024 + bn + tx * 2;
            dst[0] = acc[i][0];
            dst[1] = acc[i][1];
        }
        return;
    }

    // ---- attention for batch b ------------------------------------------
    const int b = blockIdx.x;
    const bool active = (lengths[b] - 1) > t;

    if (!active) {
        if (tid < Lc)
            alpha_out[((size_t)b * TMAX + t) * Lc + tid] = 0.f;
        return;
    }

    // de = bcat[0:512] + sum of split-K partials
    {
        int i0 = tid * 2;
        float d0 = g_bcat[i0], d1 = g_bcat[i0 + 1];
        #pragma unroll
        for (int s = 0; s < NSPLIT; ++s) {
            const float* hp = g_hp + ((size_t)s * Bc + b) * NCAT;
            d0 += hp[i0]; d1 += hp[i0 + 1];
        }
        s_de[i0] = d0; s_de[i0 + 1] = d1;
        float2 w = *reinterpret_cast<const float2*>(Wfull + i0);
        s_wf[i0] = w.x; s_wf[i0 + 1] = w.y;
    }
    __syncthreads();

    // scores: one warp per l
    const int warp = tid >> 5, lane = tid & 31;
    for (int l = warp; l < Lc; l += 8) {
        const float* ea = g_en_att + ((size_t)b * Lc + l) * Ac;
        float s = 0.f;
        #pragma unroll 4
        for (int a = lane; a < Ac; a += 32)
            s += tanh_fast(ea[a] + s_de[a]) * s_wf[a];
        #pragma unroll
        for (int o = 16; o > 0; o >>= 1)
            s += __shfl_xor_sync(0xffffffffu, s, o);
        if (lane == 0) s_sc[l] = s;
    }
    __syncthreads();

    // softmax over 196
    float v = (tid < Lc) ? s_sc[tid] : -3.4e38f;
    s_red[tid] = v; __syncthreads();
    for (int s = 128; s > 0; s >>= 1) {
        if (tid < s) s_red[tid] = fmaxf(s_red[tid], s_red[tid + s]);
        __syncthreads();
    }
    float mx = s_red[0]; __syncthreads();
    float e = (tid < Lc) ? __expf(v - mx) : 0.f;
    s_red[tid] = e; __syncthreads();
    for (int s = 128; s > 0; s >>= 1) {
        if (tid < s) s_red[tid] += s_red[tid + s];
        __syncthreads();
    }
    float inv = 1.f / s_red[0];
    if (tid < Lc) {
        float a = e * inv;
        s_sc[tid] = a;
        alpha_out[((size_t)b * TMAX + t) * Lc + tid] = a;
    }
    __syncthreads();

    // z[f] = (sum_l feat[b,l,f] * alpha[l]) * sigmoid(fb[f])
    const float* fp = features + (size_t)b * Lc * Fc;
    const int f0 = tid * 2;
    float a0 = 0.f, a1 = 0.f;
    #pragma unroll 4
    for (int l = 0; l < Lc; ++l) {
        float al = s_sc[l];
        float2 fv = *reinterpret_cast<const float2*>(fp + (size_t)l * Fc + f0);
        a0 += fv.x * al; a1 += fv.y * al;
    }
    float fb0 = g_bcat[512 + f0], fb1 = g_bcat[512 + f0 + 1];
    #pragma unroll
    for (int s = 0; s < NSPLIT; ++s) {
        const float* hp = g_hp + ((size_t)s * Bc + b) * NCAT + 512;
        fb0 += hp[f0]; fb1 += hp[f0 + 1];
    }
    g_xz[b * Fc + f0]     = a0 * sigmoid_fast(fb0);
    g_xz[b * Fc + f0 + 1] = a1 * sigmoid_fast(fb1);
}

// ---------------------------------------------------------------------------
// zlstm: gate-aligned z-GEMM with fused LSTM-cell epilogue.
// grid = 256 CTAs; CTA j owns n in [j*2, j*2+2) across all 4 gates (8 cols).
// gates = z @ Wihz^T (full K) + bcat + embg[t] + sum(hproj hh partials)
// ---------------------------------------------------------------------------
__global__ __launch_bounds__(256) void zlstm(
    const float* __restrict__ W_ih,
    const int*   __restrict__ lengths, int t)
{
    const int j = blockIdx.x;                 // n2 = j*2
    const int n2 = j * 2;
    const int tid = threadIdx.x;

    __shared__ float As[2][16][64];
    __shared__ float Bs[2][16][8];
    __shared__ float sg[64][8];

    // A loader: 64x16 tile, 4 floats/thread
    const int arow = tid >> 2, acol = (tid & 3) * 4;
    const float* aptr = g_xz + (size_t)arow * 512 + acol;

    // B loader: 8 rows x 16 k, threads 0..127, one float each
    const int brow = (tid >> 4) & 7;          // valid when tid < 128
    const int bcol = tid & 15;
    const int bgate = brow >> 1, bnl = brow & 1;
    const float* bptr = W_ih + (size_t)(bgate * 512 + n2 + bnl) * 1024
                             + 512 + bcol;

    // compute mapping: 32 row-groups x 8 cols
    const int tx = tid & 7, ty = tid >> 3;
    float acc0 = 0.f, acc1 = 0.f;

    float4 av = *reinterpret_cast<const float4*>(aptr);
    float bvv = (tid < 128) ? *bptr : 0.f;
    As[0][acol + 0][arow] = av.x; As[0][acol + 1][arow] = av.y;
    As[0][acol + 2][arow] = av.z; As[0][acol + 3][arow] = av.w;
    if (tid < 128) Bs[0][bcol][brow] = bvv;
    __syncthreads();

    const int nt = 512 / 16;
    for (int it = 0; it < nt; ++it) {
        const int cur = it & 1;
        if (it + 1 < nt) {
            av = *reinterpret_cast<const float4*>(aptr + (it + 1) * 16);
            if (tid < 128) bvv = bptr[(it + 1) * 16];
        }
        #pragma unroll
        for (int k = 0; k < 16; ++k) {
            float2 a2 = *reinterpret_cast<const float2*>(&As[cur][k][ty * 2]);
            float bb = Bs[cur][k][tx];
            acc0 += a2.x * bb;
            acc1 += a2.y * bb;
        }
        if (it + 1 < nt) {
            const int nxt = cur ^ 1;
            As[nxt][acol + 0][arow] = av.x; As[nxt][acol + 1][arow] = av.y;
            As[nxt][acol + 2][arow] = av.z; As[nxt][acol + 3][arow] = av.w;
            if (tid < 128) Bs[nxt][bcol][brow] = bvv;
        }
        __syncthreads();
    }

    // stage gate partial results: sg[b][gate*2 + nl]
    sg[ty * 2 + 0][tx] = acc0;
    sg[ty * 2 + 1][tx] = acc1;
    __syncthreads();

    // LSTM epilogue: threads 0..127 each own one (b, nl)
    if (tid < 128) {
        const int b = tid >> 1, nl = tid & 1;
        if ((lengths[b] - 1) > t) {
            const int n = n2 + nl;
            float gate[4];
            #pragma unroll
            for (int g = 0; g < 4; ++g) {
                const int col = g * 512 + n;
                float v = sg[b][g * 2 + nl]
                        + g_bcat[1024 + col]
                        + g_embg[((size_t)t * Bc + b) * 2048 + col];
                #pragma unroll
                for (int s = 0; s < NSPLIT; ++s)
                    v += g_hp[((size_t)s * Bc + b) * NCAT + 1024 + col];
                gate[g] = v;
            }
            float c  = g_hc[b * 1024 + 512 + n];
            float si = sigmoid_fast(gate[0]);
            float sf = sigmoid_fast(gate[1]);
            float so = sigmoid_fast(gate[3]);
            float cn = sf * c + si * tanhf(gate[2]);
            float hn = so * tanhf(cn);
            g_hnew_all[((size_t)t * Bc + b) * Hc + n] = hn;
            g_hc[b * 1024 + n]       = hn;
            g_hc[b * 1024 + 512 + n] = cn;
        }
    }
}

// ---------------------------------------------------------------------------
// tf32 tensor-core NT GEMM: C[M,N] = A[M,K] @ B[N,K]^T (+bias)
//   mma.sync.m16n8k8, BM=64, BN=64, BK=32, 256 threads (8 warps, 4x2).
//   MODE 0: normal store; MODE 2: vocab scatter (row m -> t=m/64, b=m%64),
//   inactive rows forced to 0. Requires: M%64==0, K%32==0, N even.
// ---------------------------------------------------------------------------
template<int MODE>
__global__ __launch_bounds__(256) void gemm_tc(
    int M, int N, int K,
    const float* __restrict__ A,
    const float* __restrict__ B, int ldB,
    const float* __restrict__ bias,
    float* __restrict__ C, int ldC,
    const int* __restrict__ lengths, float* __restrict__ predBase)
{
    constexpr int BM = 64, BN = 64, BK = 32, PAD = 4;
    __shared__ unsigned As[2][BM][BK + PAD];
    __shared__ unsigned Bs[2][BN][BK + PAD];

    const int tid = threadIdx.x;
    const int lane = tid & 31, wid = tid >> 5;
    const int wm = wid & 3, wn = wid >> 2;       // warp tile: rows 16, cols 32
    const int g = lane >> 2, tg = lane & 3;
    const int bm = blockIdx.y * BM, bn = blockIdx.x * BN;

    const int lr = tid >> 2;                     // 0..63
    const int lc = (tid & 3) * 8;                // 0,8,16,24
    const float* ap = A + (size_t)(bm + lr) * K + lc;
    const float* bp = B + (size_t)(bn + lr) * ldB + lc;
    const bool bval = (bn + lr) < N;

    float acc[4][4];
    #pragma unroll
    for (int i = 0; i < 4; ++i)
        #pragma unroll
        for (int j = 0; j < 4; ++j) acc[i][j] = 0.f;

    float4 a0v, a1v, b0v, b1v;

    a0v = *reinterpret_cast<const float4*>(ap);
    a1v = *reinterpret_cast<const float4*>(ap + 4);
    b0v = bval ? *reinterpret_cast<const float4*>(bp)     : make_float4(0,0,0,0);
    b1v = bval ? *reinterpret_cast<const float4*>(bp + 4) : make_float4(0,0,0,0);
    As[0][lr][lc + 0] = f2tf32(a0v.x); As[0][lr][lc + 1] = f2tf32(a0v.y);
    As[0][lr][lc + 2] = f2tf32(a0v.z); As[0][lr][lc + 3] = f2tf32(a0v.w);
    As[0][lr][lc + 4] = f2tf32(a1v.x); As[0][lr][lc + 5] = f2tf32(a1v.y);
    As[0][lr][lc + 6] = f2tf32(a1v.z); As[0][lr][lc + 7] = f2tf32(a1v.w);
    Bs[0][lr][lc + 0] = f2tf32(b0v.x); Bs[0][lr][lc + 1] = f2tf32(b0v.y);
    Bs[0][lr][lc + 2] = f2tf32(b0v.z); Bs[0][lr][lc + 3] = f2tf32(b0v.w);
    Bs[0][lr][lc + 4] = f2tf32(b1v.x); Bs[0][lr][lc + 5] = f2tf32(b1v.y);
    Bs[0][lr][lc + 6] = f2tf32(b1v.z); Bs[0][lr][lc + 7] = f2tf32(b1v.w);
    __syncthreads();

    const int nt = K / BK;
    for (int it = 0; it < nt; ++it) {
        const int cur = it & 1;
        if (it + 1 < nt) {
            a0v = *reinterpret_cast<const float4*>(ap + (it + 1) * BK);
            a1v = *reinterpret_cast<const float4*>(ap + (it + 1) * BK + 4);
            b0v = bval ? *reinterpret_cast<const float4*>(bp + (it + 1) * BK)
                       : make_float4(0,0,0,0);
            b1v = bval ? *reinterpret_cast<const float4*>(bp + (it + 1) * BK + 4)
                       : make_float4(0,0,0,0);
        }
        #pragma unroll
        for (int ks = 0; ks < 4; ++ks) {
            const int k0 = ks * 8;
            unsigned fa0 = As[cur][wm * 16 + g][k0 + tg];
            unsigned fa1 = As[cur][wm * 16 + g + 8][k0 + tg];
            unsigned fa2 = As[cur][wm * 16 + g][k0 + tg + 4];
            unsigned fa3 = As[cur][wm * 16 + g + 8][k0 + tg + 4];
            #pragma unroll
            for (int t8 = 0; t8 < 4; ++t8) {
                unsigned fb0 = Bs[cur][wn * 32 + t8 * 8 + g][k0 + tg];
                unsigned fb1 = Bs[cur][wn * 32 + t8 * 8 + g][k0 + tg + 4];
                asm volatile(
                    "mma.sync.aligned.m16n8k8.row.col.f32.tf32.tf32.f32 "
                    "{%0,%1,%2,%3}, {%4,%5,%6,%7}, {%8,%9}, {%0,%1,%2,%3};"
                    : "+f"(acc[t8][0]), "+f"(acc[t8][1]),
                      "+f"(acc[t8][2]), "+f"(acc[t8][3])
                    : "r"(fa0), "r"(fa1), "r"(fa2), "r"(fa3),
                      "r"(fb0), "r"(fb1));
            }
        }
        if (it + 1 < nt) {
            const int nxt = cur ^ 1;
            As[nxt][lr][lc + 0] = f2tf32(a0v.x); As[nxt][lr][lc + 1] = f2tf32(a0v.y);
            As[nxt][lr][lc + 2] = f2tf32(a0v.z); As[nxt][lr][lc + 3] = f2tf32(a0v.w);
            As[nxt][lr][lc + 4] = f2tf32(a1v.x); As[nxt][lr][lc + 5] = f2tf32(a1v.y);
            As[nxt][lr][lc + 6] = f2tf32(a1v.z); As[nxt][lr][lc + 7] = f2tf32(a1v.w);
            Bs[nxt][lr][lc + 0] = f2tf32(b0v.x); Bs[nxt][lr][lc + 1] = f2tf32(b0v.y);
            Bs[nxt][lr][lc + 2] = f2tf32(b0v.z); Bs[nxt][lr][lc + 3] = f2tf32(b0v.w);
            Bs[nxt][lr][lc + 4] = f2tf32(b1v.x); Bs[nxt][lr][lc + 5] = f2tf32(b1v.y);
            Bs[nxt][lr][lc + 6] = f2tf32(b1v.z); Bs[nxt][lr][lc + 7] = f2tf32(b1v.w);
        }
        __syncthreads();
    }

    #pragma unroll
    for (int t8 = 0; t8 < 4; ++t8) {
        const int col = bn + wn * 32 + t8 * 8 + 2 * tg;
        if (col >= N) continue;                  // N even -> col+1 < N too
        float bb0 = bias ? bias[col]     : 0.f;
        float bb1 = bias ? bias[col + 1] : 0.f;
        #pragma unroll
        for (int half = 0; half < 2; ++half) {
            const int m = bm + wm * 16 + g + half * 8;
            float v0 = acc[t8][half * 2 + 0] + bb0;
            float v1 = acc[t8][half * 2 + 1] + bb1;
            float* dst;
            if (MODE == 2) {
                const int b = m & 63, t = m >> 6;
                if (!((lengths[b] - 1) > t)) { v0 = 0.f; v1 = 0.f; }
                dst = predBase + ((size_t)b * TMAX + t) * Vc + col;
            } else {
                dst = C + (size_t)m * ldC + col;
            }
            *reinterpret_cast<float2*>(dst) = make_float2(v0, v1);
        }
    }
}

// ---------------------------------------------------------------------------
// Host driver (graph-capturable: kernel launches only)
// ---------------------------------------------------------------------------
extern "C" void kernel_launch(void* const* d_in, const int* in_sizes, int n_in,
                              void* d_out, int out_size)
{
    const float* features = (const float*)d_in[0];
    const int*   captions = (const int*)  d_in[1];
    const int*   lengths  = (const int*)  d_in[2];
    const float* W_emb    = (const float*)d_in[3];
    const float* W_enc    = (const float*)d_in[4];
    const float* b_enc    = (const float*)d_in[5];
    const float* W_dec    = (const float*)d_in[6];
    const float* b_dec    = (const float*)d_in[7];
    const float* W_full   = (const float*)d_in[8];
    /* d_in[9] = b_full: softmax shift-invariant, unused */
    const float* W_fbeta  = (const float*)d_in[10];
    const float* b_fbeta  = (const float*)d_in[11];
    const float* W_ih     = (const float*)d_in[12];
    const float* W_hh     = (const float*)d_in[13];
    const float* b_ih     = (const float*)d_in[14];
    const float* b_hh     = (const float*)d_in[15];
    const float* W_out    = (const float*)d_in[16];
    const float* b_out    = (const float*)d_in[17];
    const float* W_init_h = (const float*)d_in[18];
    const float* b_init_h = (const float*)d_in[19];
    const float* W_init_c = (const float*)d_in[20];
    const float* b_init_c = (const float*)d_in[21];

    float* out       = (float*)d_out;
    float* alpha_out = out + PRED_SZ;

    float *p_en_att, *p_meanf, *p_hc, *p_hp, *p_ip, *p_xz,
          *p_Wcat, *p_Winit, *p_xemb, *p_embg, *p_hnew_all;
    cudaGetSymbolAddress((void**)&p_en_att,   g_en_att);
    cudaGetSymbolAddress((void**)&p_meanf,    g_meanf);
    cudaGetSymbolAddress((void**)&p_hc,       g_hc);
    cudaGetSymbolAddress((void**)&p_hp,       g_hp);
    cudaGetSymbolAddress((void**)&p_ip,       g_ip);
    cudaGetSymbolAddress((void**)&p_xz,       g_xz);
    cudaGetSymbolAddress((void**)&p_Wcat,     g_Wcat);
    cudaGetSymbolAddress((void**)&p_Winit,    g_Winit);
    cudaGetSymbolAddress((void**)&p_xemb,     g_xemb);
    cudaGetSymbolAddress((void**)&p_embg,     g_embg);
    cudaGetSymbolAddress((void**)&p_hnew_all, g_hnew_all);

    // ---- precompute -------------------------------------------------------
    build_cat<<<(NCAT * Hc + 255) / 256, 256>>>(W_dec, W_fbeta, W_hh,
                                                b_dec, b_fbeta, b_ih, b_hh);
    build_init<<<(1024 * Fc + 255) / 256, 256>>>(W_init_h, W_init_c,
                                                 b_init_h, b_init_c);
    mean_feat<<<Bc, Fc>>>(features);
    embed_all<<<dim3(Bc, TMAX), Ec>>>(W_emb, captions);

    // h0/c0: split-K GEMM + combine (exact fp32)
    gemm_splitk<<<dim3(1024 / 32, NSPLIT), 256>>>(
        1024, Fc, p_meanf, Fc, p_Winit, Fc, p_ip, 1024);
    combine_init<<<Bc, 1024>>>();

    // embedding gates (all steps): [1984, 2048] = xemb @ W_ih[:, 0:512]^T  (tf32)
    gemm_tc<0><<<dim3(2048 / 64, TMAX), 256>>>(
        TMAX * Bc, 2048, Ec, p_xemb, W_ih, Ec + Fc, nullptr,
        p_embg, 2048, nullptr, nullptr);

    // attention keys: [12544, 512] = feat_r @ W_enc^T + b_enc  (tf32)
    gemm_tc<0><<<dim3(Ac / 64, (Bc * Lc) / 64), 256>>>(
        Bc * Lc, Ac, Fc, features, W_enc, Fc, b_enc,
        p_en_att, Ac, nullptr, nullptr);

    // ---- 31 recurrent steps (exact fp32, 3 launches each) ------------------
    for (int t = 0; t < TMAX; ++t) {
        // de | fbeta projections only (first 1024 Wcat rows)
        gemm_splitk<<<dim3(1024 / 32, NSPLIT), 256>>>(
            1024, Hc, p_hc, 1024, p_Wcat, Hc, p_hp, NCAT);

        // attention (blocks 0..63) + hh-gates GEMM (blocks 64..319)
        att_hh<<<320, 256>>>(features, W_full, lengths, alpha_out, t);

        // z-GEMM + fused LSTM cell
        zlstm<<<256, 256>>>(W_ih, lengths, t);
    }

    // ---- batched vocab projection for all 31 steps (tf32) -----------------
    gemm_tc<2><<<dim3((Vc + 63) / 64, TMAX), 256>>>(
        TMAX * Bc, Vc, Hc, p_hnew_all, W_out, Hc, b_out,
        nullptr, 0, lengths, out);
}

// round 10
// speedup vs baseline: 1.0879x; 1.0879x over previous
#include <cuda_runtime.h>
#include <math.h>

// ---------------------------------------------------------------------------
// Problem constants
// ---------------------------------------------------------------------------
namespace {
constexpr int Bc = 64, Tc = 32, TMAX = 31;
constexpr int Fc = 512, Lc = 196, Ec = 512, Hc = 512, Ac = 512, Vc = 10000;
constexpr int NCAT = 3072;            // de(512) | fbeta(512) | hh gates(2048)
constexpr long long PRED_SZ = (long long)Bc * TMAX * Vc;   // 19,840,000
constexpr int NCTA = 296;             // persistent grid: 2 CTAs per SM
}

// ---------------------------------------------------------------------------
// Static scratch (no allocations allowed)
// ---------------------------------------------------------------------------
__device__ float g_en_att[Bc * Lc * Ac];          // [B*L, A]
__device__ float g_meanf[Bc * Fc];
__device__ float g_hc[Bc * 1024];                 // h = cols[0:512), c = cols[512:1024)
__device__ float g_hp[4 * Bc * NCAT];             // hproj partials (de/fb: 4 planes, hh: 2)
__device__ float g_zp[2 * Bc * 2048];             // z-gate partials (2 planes)
__device__ float g_xz[Bc * Fc];                   // gated context z
__device__ float g_Wcat[NCAT * Hc];               // [W_dec ; W_fbeta ; W_hh]
__device__ float g_bcat[NCAT];
__device__ float g_Winit[1024 * Fc];              // [W_init_h ; W_init_c]
__device__ float g_binit[1024];
__device__ float g_xemb[TMAX * Bc * Ec];          // gathered embeddings
__device__ float g_embg[TMAX * Bc * 2048];        // emb @ W_ih_emb^T
__device__ float g_hnew_all[TMAX * Bc * Hc];      // unmasked h_new per step
__device__ volatile unsigned g_barrier;           // monotonic grid barrier

__device__ __forceinline__ float tanh_fast(float x) {
    float y;
    asm("tanh.approx.f32 %0, %1;" : "=f"(y) : "f"(x));
    return y;
}
__device__ __forceinline__ float sigmoid_fast(float x) {
    return 1.0f / (1.0f + __expf(-x));
}
__device__ __forceinline__ unsigned f2tf32(float x) {
    unsigned r;
    asm("cvt.rna.tf32.f32 %0, %1;" : "=r"(r) : "f"(x));
    return r;
}

// ---------------------------------------------------------------------------
// Launch 1: weight packing + barrier reset (merged)
// ---------------------------------------------------------------------------
__global__ void prep_weights(const float* __restrict__ Wdec,
                             const float* __restrict__ Wfb,
                             const float* __restrict__ Whh,
                             const float* __restrict__ bdec,
                             const float* __restrict__ bfb,
                             const float* __restrict__ bih,
                             const float* __restrict__ bhh,
                             const float* __restrict__ Wih_,
                             const float* __restrict__ Wic_,
                             const float* __restrict__ bih0,
                             const float* __restrict__ bic0)
{
    int idx = blockIdx.x * 256 + threadIdx.x;
    if (idx == 0) g_barrier = 0u;
    if (idx < NCAT * Hc) {
        int n = idx / Hc, k = idx % Hc;
        float v;
        if (n < 512)       v = Wdec[n * Hc + k];
        else if (n < 1024) v = Wfb[(n - 512) * Hc + k];
        else               v = Whh[(n - 1024) * Hc + k];
        g_Wcat[idx] = v;
    }
    if (idx < NCAT) {
        float v;
        if (idx < 512)       v = bdec[idx];
        else if (idx < 1024) v = bfb[idx - 512];
        else                 v = bih[idx - 1024] + bhh[idx - 1024];
        g_bcat[idx] = v;
    }
    if (idx < 1024 * Fc) {
        int n = idx / Fc, k = idx % Fc;
        g_Winit[idx] = (n < 512) ? Wih_[n * Fc + k] : Wic_[(n - 512) * Fc + k];
    }
    if (idx < 1024)
        g_binit[idx] = (idx < 512) ? bih0[idx] : bic0[idx - 512];
}

// ---------------------------------------------------------------------------
// Launch 2: mean over L + embedding gather (merged)
// blocks 0..63 = mean_feat(b); blocks 64.. = embed(t, b)
// ---------------------------------------------------------------------------
__global__ void gather(const float* __restrict__ feat,
                       const float* __restrict__ Wemb,
                       const int* __restrict__ captions)
{
    if (blockIdx.x < 64) {
        int b = blockIdx.x, f = threadIdx.x;   // 512 threads
        const float* p = feat + (size_t)b * Fc * Lc + (size_t)f * Lc;
        float s = 0.f;
        #pragma unroll 4
        for (int l = 0; l < Lc; ++l) s += p[l];
        g_meanf[b * Fc + f] = s * (1.0f / (float)Lc);
    } else {
        int u = blockIdx.x - 64;
        int t = u >> 6, b = u & 63, e = threadIdx.x;
        int tok = captions[b * Tc + t];
        g_xemb[((size_t)t * Bc + b) * Ec + e] = Wemb[(size_t)tok * Ec + e];
    }
}

// ---------------------------------------------------------------------------
// 64x32 fp32 tile GEMM helper (double-buffered, BK=16, 256 threads)
//   C(64,32) = A(64, kslice) @ Brow(32, kslice)^T (+bias)
// ---------------------------------------------------------------------------
__device__ __forceinline__ void tile_gemm(
    const float* __restrict__ A, int ldA,
    const float* __restrict__ Brow, int ldB,
    int koff, int ktiles,
    const float* __restrict__ bias,
    float* __restrict__ dst, int ldC,
    float (&As)[2][16][64], float (&Bs)[2][16][32])
{
    const int tid = threadIdx.x;
    const int tx = tid & 15, ty = tid >> 4;
    const int arow = tid >> 2, acol = (tid & 3) * 4;
    const int brow = tid >> 3, bcol = (tid & 7) * 2;

    const float* aptr = A + (size_t)arow * ldA + koff + acol;
    const float* bptr = Brow + (size_t)brow * ldB + koff + bcol;

    float acc[4][2];
    #pragma unroll
    for (int i = 0; i < 4; ++i) { acc[i][0] = 0.f; acc[i][1] = 0.f; }

    float4 av = *reinterpret_cast<const float4*>(aptr);
    float2 bv = *reinterpret_cast<const float2*>(bptr);
    As[0][acol + 0][arow] = av.x; As[0][acol + 1][arow] = av.y;
    As[0][acol + 2][arow] = av.z; As[0][acol + 3][arow] = av.w;
    Bs[0][bcol + 0][brow] = bv.x; Bs[0][bcol + 1][brow] = bv.y;
    __syncthreads();

    for (int it = 0; it < ktiles; ++it) {
        const int cur = it & 1;
        if (it + 1 < ktiles) {
            av = *reinterpret_cast<const float4*>(aptr + (it + 1) * 16);
            bv = *reinterpret_cast<const float2*>(bptr + (it + 1) * 16);
        }
        #pragma unroll
        for (int k = 0; k < 16; ++k) {
            float4 a4 = *reinterpret_cast<const float4*>(&As[cur][k][ty * 4]);
            float2 b2 = *reinterpret_cast<const float2*>(&Bs[cur][k][tx * 2]);
            acc[0][0] += a4.x * b2.x; acc[0][1] += a4.x * b2.y;
            acc[1][0] += a4.y * b2.x; acc[1][1] += a4.y * b2.y;
            acc[2][0] += a4.z * b2.x; acc[2][1] += a4.z * b2.y;
            acc[3][0] += a4.w * b2.x; acc[3][1] += a4.w * b2.y;
        }
        if (it + 1 < ktiles) {
            const int nxt = cur ^ 1;
            As[nxt][acol + 0][arow] = av.x; As[nxt][acol + 1][arow] = av.y;
            As[nxt][acol + 2][arow] = av.z; As[nxt][acol + 3][arow] = av.w;
            Bs[nxt][bcol + 0][brow] = bv.x; Bs[nxt][bcol + 1][brow] = bv.y;
        }
        __syncthreads();
    }

    float b0 = bias ? bias[tx * 2 + 0] : 0.f;
    float b1 = bias ? bias[tx * 2 + 1] : 0.f;
    #pragma unroll
    for (int i = 0; i < 4; ++i) {
        float* d = dst + (size_t)(ty * 4 + i) * ldC + tx * 2;
        d[0] = acc[i][0] + b0;
        d[1] = acc[i][1] + b1;
    }
}

// ---------------------------------------------------------------------------
// Persistent step loop: h0/c0 init + all 31 steps in ONE launch.
// grid = 296 CTAs x 256 threads (2/SM co-resident; spin barrier).
// ---------------------------------------------------------------------------
__device__ __forceinline__ void gsync(unsigned& epoch)
{
    __syncthreads();
    if (threadIdx.x == 0) {
        __threadfence();
        atomicAdd((unsigned*)&g_barrier, 1u);
        epoch += NCTA;
        while (g_barrier < epoch) { }
        __threadfence();
    }
    __syncthreads();
}

__global__ __launch_bounds__(256, 2) void step_loop(
    const float* __restrict__ features,
    const float* __restrict__ W_ih,
    const float* __restrict__ Wfull,
    const int*   __restrict__ lengths,
    float* __restrict__ alpha_out)
{
    __shared__ float As[2][16][64];
    __shared__ float Bs[2][16][32];
    __shared__ float s_de[Ac];
    __shared__ float s_wf[Ac];
    __shared__ float s_sc[256];
    __shared__ float s_red[256];

    const int bid = blockIdx.x;
    const int tid = threadIdx.x;
    unsigned epoch = 0;

    // ---- Phase 0: h0/c0 = meanf @ Winit^T + binit (32 units, full K) ------
    if (bid < 32) {
        const int n0 = bid * 32;
        tile_gemm(g_meanf, 512, g_Winit + (size_t)n0 * 512, 512, 0, 32,
                  g_binit + n0, g_hc + n0, 1024, As, Bs);
    }
    gsync(epoch);

    for (int t = 0; t < TMAX; ++t) {
        // ---- Phase A: de/fbeta partials, 4 splits (128 units) -------------
        if (bid < 128) {
            const int s = bid >> 5, tn = bid & 31;
            const int n0 = tn * 32;
            tile_gemm(g_hc, 1024, g_Wcat + (size_t)n0 * 512, 512,
                      s * 128, 8, nullptr,
                      g_hp + (size_t)s * Bc * NCAT + n0, NCAT, As, Bs);
        }
        gsync(epoch);

        // ---- Phase B: attention (bid<64)  ||  hh-gates GEMM (64<=bid<192) -
        if (bid < 64) {
            const int b = bid;
            const bool active = (lengths[b] - 1) > t;
            if (!active) {
                if (tid < Lc)
                    alpha_out[((size_t)b * TMAX + t) * Lc + tid] = 0.f;
            } else {
                // de = bcat[0:512] + 4 partial planes
                {
                    int i0 = tid * 2;
                    float d0 = g_bcat[i0], d1 = g_bcat[i0 + 1];
                    #pragma unroll
                    for (int s = 0; s < 4; ++s) {
                        const float* hp = g_hp + ((size_t)s * Bc + b) * NCAT;
                        d0 += hp[i0]; d1 += hp[i0 + 1];
                    }
                    s_de[i0] = d0; s_de[i0 + 1] = d1;
                    float2 w = *reinterpret_cast<const float2*>(Wfull + i0);
                    s_wf[i0] = w.x; s_wf[i0 + 1] = w.y;
                }
                __syncthreads();

                const int warp = tid >> 5, lane = tid & 31;
                for (int l = warp; l < Lc; l += 8) {
                    const float* ea = g_en_att + ((size_t)b * Lc + l) * Ac;
                    float s = 0.f;
                    #pragma unroll 4
                    for (int a = lane; a < Ac; a += 32)
                        s += tanh_fast(ea[a] + s_de[a]) * s_wf[a];
                    #pragma unroll
                    for (int o = 16; o > 0; o >>= 1)
                        s += __shfl_xor_sync(0xffffffffu, s, o);
                    if (lane == 0) s_sc[l] = s;
                }
                __syncthreads();

                float v = (tid < Lc) ? s_sc[tid] : -3.4e38f;
                s_red[tid] = v; __syncthreads();
                for (int s = 128; s > 0; s >>= 1) {
                    if (tid < s) s_red[tid] = fmaxf(s_red[tid], s_red[tid + s]);
                    __syncthreads();
                }
                float mx = s_red[0]; __syncthreads();
                float e = (tid < Lc) ? __expf(v - mx) : 0.f;
                s_red[tid] = e; __syncthreads();
                for (int s = 128; s > 0; s >>= 1) {
                    if (tid < s) s_red[tid] += s_red[tid + s];
                    __syncthreads();
                }
                float inv = 1.f / s_red[0];
                if (tid < Lc) {
                    float a = e * inv;
                    s_sc[tid] = a;
                    alpha_out[((size_t)b * TMAX + t) * Lc + tid] = a;
                }
                __syncthreads();

                const float* fp = features + (size_t)b * Lc * Fc;
                const int f0 = tid * 2;
                float a0 = 0.f, a1 = 0.f;
                #pragma unroll 4
                for (int l = 0; l < Lc; ++l) {
                    float al = s_sc[l];
                    float2 fv = *reinterpret_cast<const float2*>(
                        fp + (size_t)l * Fc + f0);
                    a0 += fv.x * al; a1 += fv.y * al;
                }
                float fb0 = g_bcat[512 + f0], fb1 = g_bcat[512 + f0 + 1];
                #pragma unroll
                for (int s = 0; s < 4; ++s) {
                    const float* hp = g_hp + ((size_t)s * Bc + b) * NCAT + 512;
                    fb0 += hp[f0]; fb1 += hp[f0 + 1];
                }
                g_xz[b * Fc + f0]     = a0 * sigmoid_fast(fb0);
                g_xz[b * Fc + f0 + 1] = a1 * sigmoid_fast(fb1);
            }
        } else if (bid < 192) {
            const int u = bid - 64;
            const int s = u >> 6, tn = u & 63;     // 2 splits x 64 tiles
            const int n0 = 1024 + tn * 32;
            tile_gemm(g_hc, 1024, g_Wcat + (size_t)n0 * 512, 512,
                      s * 256, 16, nullptr,
                      g_hp + (size_t)s * Bc * NCAT + n0, NCAT, As, Bs);
        }
        gsync(epoch);

        // ---- Phase C: z-gate partials, 2 splits (128 units) ---------------
        if (bid < 128) {
            const int s = bid >> 6, tn = bid & 63;
            const int n0 = tn * 32;
            tile_gemm(g_xz, 512, W_ih + (size_t)n0 * 1024 + 512, 1024,
                      s * 256, 16, nullptr,
                      g_zp + (size_t)s * Bc * 2048 + n0, 2048, As, Bs);
        }
        gsync(epoch);

        // ---- Phase D: LSTM cell (64 units) --------------------------------
        if (bid < 64) {
            const int b = bid;
            const bool active = (lengths[b] - 1) > t;
            #pragma unroll
            for (int half = 0; half < 2; ++half) {
                const int n = tid + half * 256;
                float gate[4];
                #pragma unroll
                for (int g = 0; g < 4; ++g) {
                    const int col = g * 512 + n;
                    float v = g_bcat[1024 + col]
                            + g_embg[((size_t)t * Bc + b) * 2048 + col]
                            + g_hp[(size_t)0 * Bc * NCAT + (size_t)b * NCAT + 1024 + col]
                            + g_hp[(size_t)1 * Bc * NCAT + (size_t)b * NCAT + 1024 + col]
                            + g_zp[(size_t)0 * Bc * 2048 + (size_t)b * 2048 + col]
                            + g_zp[(size_t)1 * Bc * 2048 + (size_t)b * 2048 + col];
                    gate[g] = v;
                }
                float c  = g_hc[b * 1024 + 512 + n];
                float si = sigmoid_fast(gate[0]);
                float sf = sigmoid_fast(gate[1]);
                float so = sigmoid_fast(gate[3]);
                float cn = sf * c + si * tanhf(gate[2]);
                float hn = so * tanhf(cn);
                g_hnew_all[((size_t)t * Bc + b) * Hc + n] = hn;
                if (active) {
                    g_hc[b * 1024 + n]       = hn;
                    g_hc[b * 1024 + 512 + n] = cn;
                }
            }
        }
        gsync(epoch);
    }
}

// ---------------------------------------------------------------------------
// tf32 tensor-core NT GEMM (unchanged from R8): C = A @ B^T (+bias)
//   MODE 0: normal store; MODE 2: vocab scatter, inactive rows zeroed.
// ---------------------------------------------------------------------------
template<int MODE>
__global__ __launch_bounds__(256) void gemm_tc(
    int M, int N, int K,
    const float* __restrict__ A,
    const float* __restrict__ B, int ldB,
    const float* __restrict__ bias,
    float* __restrict__ C, int ldC,
    const int* __restrict__ lengths, float* __restrict__ predBase)
{
    constexpr int BM = 64, BN = 64, BK = 32, PAD = 4;
    __shared__ unsigned As[2][BM][BK + PAD];
    __shared__ unsigned Bs[2][BN][BK + PAD];

    const int tid = threadIdx.x;
    const int lane = tid & 31, wid = tid >> 5;
    const int wm = wid & 3, wn = wid >> 2;
    const int g = lane >> 2, tg = lane & 3;
    const int bm = blockIdx.y * BM, bn = blockIdx.x * BN;

    const int lr = tid >> 2;
    const int lc = (tid & 3) * 8;
    const float* ap = A + (size_t)(bm + lr) * K + lc;
    const float* bp = B + (size_t)(bn + lr) * ldB + lc;
    const bool bval = (bn + lr) < N;

    float acc[4][4];
    #pragma unroll
    for (int i = 0; i < 4; ++i)
        #pragma unroll
        for (int j = 0; j < 4; ++j) acc[i][j] = 0.f;

    float4 a0v, a1v, b0v, b1v;

    a0v = *reinterpret_cast<const float4*>(ap);
    a1v = *reinterpret_cast<const float4*>(ap + 4);
    b0v = bval ? *reinterpret_cast<const float4*>(bp)     : make_float4(0,0,0,0);
    b1v = bval ? *reinterpret_cast<const float4*>(bp + 4) : make_float4(0,0,0,0);
    As[0][lr][lc + 0] = f2tf32(a0v.x); As[0][lr][lc + 1] = f2tf32(a0v.y);
    As[0][lr][lc + 2] = f2tf32(a0v.z); As[0][lr][lc + 3] = f2tf32(a0v.w);
    As[0][lr][lc + 4] = f2tf32(a1v.x); As[0][lr][lc + 5] = f2tf32(a1v.y);
    As[0][lr][lc + 6] = f2tf32(a1v.z); As[0][lr][lc + 7] = f2tf32(a1v.w);
    Bs[0][lr][lc + 0] = f2tf32(b0v.x); Bs[0][lr][lc + 1] = f2tf32(b0v.y);
    Bs[0][lr][lc + 2] = f2tf32(b0v.z); Bs[0][lr][lc + 3] = f2tf32(b0v.w);
    Bs[0][lr][lc + 4] = f2tf32(b1v.x); Bs[0][lr][lc + 5] = f2tf32(b1v.y);
    Bs[0][lr][lc + 6] = f2tf32(b1v.z); Bs[0][lr][lc + 7] = f2tf32(b1v.w);
    __syncthreads();

    const int nt = K / BK;
    for (int it = 0; it < nt; ++it) {
        const int cur = it & 1;
        if (it + 1 < nt) {
            a0v = *reinterpret_cast<const float4*>(ap + (it + 1) * BK);
            a1v = *reinterpret_cast<const float4*>(ap + (it + 1) * BK + 4);
            b0v = bval ? *reinterpret_cast<const float4*>(bp + (it + 1) * BK)
                       : make_float4(0,0,0,0);
            b1v = bval ? *reinterpret_cast<const float4*>(bp + (it + 1) * BK + 4)
                       : make_float4(0,0,0,0);
        }
        #pragma unroll
        for (int ks = 0; ks < 4; ++ks) {
            const int k0 = ks * 8;
            unsigned fa0 = As[cur][wm * 16 + g][k0 + tg];
            unsigned fa1 = As[cur][wm * 16 + g + 8][k0 + tg];
            unsigned fa2 = As[cur][wm * 16 + g][k0 + tg + 4];
            unsigned fa3 = As[cur][wm * 16 + g + 8][k0 + tg + 4];
            #pragma unroll
            for (int t8 = 0; t8 < 4; ++t8) {
                unsigned fb0 = Bs[cur][wn * 32 + t8 * 8 + g][k0 + tg];
                unsigned fb1 = Bs[cur][wn * 32 + t8 * 8 + g][k0 + tg + 4];
                asm volatile(
                    "mma.sync.aligned.m16n8k8.row.col.f32.tf32.tf32.f32 "
                    "{%0,%1,%2,%3}, {%4,%5,%6,%7}, {%8,%9}, {%0,%1,%2,%3};"
                    : "+f"(acc[t8][0]), "+f"(acc[t8][1]),
                      "+f"(acc[t8][2]), "+f"(acc[t8][3])
                    : "r"(fa0), "r"(fa1), "r"(fa2), "r"(fa3),
                      "r"(fb0), "r"(fb1));
            }
        }
        if (it + 1 < nt) {
            const int nxt = cur ^ 1;
            As[nxt][lr][lc + 0] = f2tf32(a0v.x); As[nxt][lr][lc + 1] = f2tf32(a0v.y);
            As[nxt][lr][lc + 2] = f2tf32(a0v.z); As[nxt][lr][lc + 3] = f2tf32(a0v.w);
            As[nxt][lr][lc + 4] = f2tf32(a1v.x); As[nxt][lr][lc + 5] = f2tf32(a1v.y);
            As[nxt][lr][lc + 6] = f2tf32(a1v.z); As[nxt][lr][lc + 7] = f2tf32(a1v.w);
            Bs[nxt][lr][lc + 0] = f2tf32(b0v.x); Bs[nxt][lr][lc + 1] = f2tf32(b0v.y);
            Bs[nxt][lr][lc + 2] = f2tf32(b0v.z); Bs[nxt][lr][lc + 3] = f2tf32(b0v.w);
            Bs[nxt][lr][lc + 4] = f2tf32(b1v.x); Bs[nxt][lr][lc + 5] = f2tf32(b1v.y);
            Bs[nxt][lr][lc + 6] = f2tf32(b1v.z); Bs[nxt][lr][lc + 7] = f2tf32(b1v.w);
        }
        __syncthreads();
    }

    #pragma unroll
    for (int t8 = 0; t8 < 4; ++t8) {
        const int col = bn + wn * 32 + t8 * 8 + 2 * tg;
        if (col >= N) continue;
        float bb0 = bias ? bias[col]     : 0.f;
        float bb1 = bias ? bias[col + 1] : 0.f;
        #pragma unroll
        for (int half = 0; half < 2; ++half) {
            const int m = bm + wm * 16 + g + half * 8;
            float v0 = acc[t8][half * 2 + 0] + bb0;
            float v1 = acc[t8][half * 2 + 1] + bb1;
            float* dst;
            if (MODE == 2) {
                const int b = m & 63, t = m >> 6;
                if (!((lengths[b] - 1) > t)) { v0 = 0.f; v1 = 0.f; }
                dst = predBase + ((size_t)b * TMAX + t) * Vc + col;
            } else {
                dst = C + (size_t)m * ldC + col;
            }
            *reinterpret_cast<float2*>(dst) = make_float2(v0, v1);
        }
    }
}

// ---------------------------------------------------------------------------
// Host driver: 6 launches total (graph-capturable)
// ---------------------------------------------------------------------------
extern "C" void kernel_launch(void* const* d_in, const int* in_sizes, int n_in,
                              void* d_out, int out_size)
{
    const float* features = (const float*)d_in[0];
    const int*   captions = (const int*)  d_in[1];
    const int*   lengths  = (const int*)  d_in[2];
    const float* W_emb    = (const float*)d_in[3];
    const float* W_enc    = (const float*)d_in[4];
    const float* b_enc    = (const float*)d_in[5];
    const float* W_dec    = (const float*)d_in[6];
    const float* b_dec    = (const float*)d_in[7];
    const float* W_full   = (const float*)d_in[8];
    /* d_in[9] = b_full: softmax shift-invariant, unused */
    const float* W_fbeta  = (const float*)d_in[10];
    const float* b_fbeta  = (const float*)d_in[11];
    const float* W_ih     = (const float*)d_in[12];
    const float* W_hh     = (const float*)d_in[13];
    const float* b_ih     = (const float*)d_in[14];
    const float* b_hh     = (const float*)d_in[15];
    const float* W_out    = (const float*)d_in[16];
    const float* b_out    = (const float*)d_in[17];
    const float* W_init_h = (const float*)d_in[18];
    const float* b_init_h = (const float*)d_in[19];
    const float* W_init_c = (const float*)d_in[20];
    const float* b_init_c = (const float*)d_in[21];

    float* out       = (float*)d_out;
    float* alpha_out = out + PRED_SZ;

    float *p_en_att, *p_xemb, *p_embg, *p_hnew_all;
    cudaGetSymbolAddress((void**)&p_en_att,   g_en_att);
    cudaGetSymbolAddress((void**)&p_xemb,     g_xemb);
    cudaGetSymbolAddress((void**)&p_embg,     g_embg);
    cudaGetSymbolAddress((void**)&p_hnew_all, g_hnew_all);

    // 1: pack weights + reset barrier
    prep_weights<<<(NCAT * Hc + 255) / 256, 256>>>(
        W_dec, W_fbeta, W_hh, b_dec, b_fbeta, b_ih, b_hh,
        W_init_h, W_init_c, b_init_h, b_init_c);

    // 2: feature mean + embedding gather
    gather<<<64 + TMAX * Bc, 512>>>(features, W_emb, captions);

    // 3: embedding gates (all steps)  [1984, 2048] = xemb @ W_ih[:, 0:512]^T
    gemm_tc<0><<<dim3(2048 / 64, TMAX), 256>>>(
        TMAX * Bc, 2048, Ec, p_xemb, W_ih, Ec + Fc, nullptr,
        p_embg, 2048, nullptr, nullptr);

    // 4: attention keys  [12544, 512] = feat_r @ W_enc^T + b_enc
    gemm_tc<0><<<dim3(Ac / 64, (Bc * Lc) / 64), 256>>>(
        Bc * Lc, Ac, Fc, features, W_enc, Fc, b_enc,
        p_en_att, Ac, nullptr, nullptr);

    // 5: the entire recurrence (h0/c0 + 31 steps), persistent
    step_loop<<<NCTA, 256>>>(features, W_ih, W_full, lengths, alpha_out);

    // 6: batched vocab projection
    gemm_tc<2><<<dim3((Vc + 63) / 64, TMAX), 256>>>(
        TMAX * Bc, Vc, Hc, p_hnew_all, W_out, Hc, b_out,
        nullptr, 0, lengths, out);
}